// round 7
// baseline (speedup 1.0000x reference)
#include <cuda_runtime.h>
#include <math.h>
#include <stdint.h>

// ---------------------------------------------------------------------------
// SparseMoE top-2-of-8, T=8192 tokens, D=1024, D_FF=4096, fp32 in/out.
// Sparse grouped-GEMM (16384 token-expert rows), tf32 mma.sync.
// All GEMM operands pre-rounded to tf32 in memory -> zero cvt in mainloops.
// BM=256 x BN=128 x BK=32, 512 threads, 3-stage cp.async pipeline.
// GEMM2 writes per-slot partials (no atomics); combine kernel sums 2 slots.
// ---------------------------------------------------------------------------

#define T_TOK 8192
#define D_IN  1024
#define D_FF  4096
#define NE    8
#define NSLOT (T_TOK * 2)
#define W_ELEMS (NE * D_IN * D_FF)     // 33.55M per weight tensor

// Scratch (device globals: no allocations allowed)
__device__ int   g_counts[NE];
__device__ int   g_base[NE];
__device__ int   g_fill[NE];
__device__ int   g_tok_e[NSLOT];
__device__ float g_tok_w[NSLOT];
__device__ int   g_tok_slot[NSLOT];             // token -> its 2 slot indices
__device__ float g_slot_w[NSLOT];
__device__ int   g_slot_token[NSLOT];
__device__ float g_h[(size_t)NSLOT * D_FF];     // 256 MB hidden acts (tf32-rounded)
__device__ float g_part[(size_t)NSLOT * D_IN];  // 64 MB per-slot weighted outputs
__device__ float g_xr[(size_t)T_TOK * D_IN];    // 32 MB rounded x
__device__ float g_w1r[(size_t)W_ELEMS];        // 128 MB rounded W1
__device__ float g_w2r[(size_t)W_ELEMS];        // 128 MB rounded W2

// Tile geometry
#define BM        256
#define BN        128
#define BK        32
#define NTHREADS  512
#define A_LDW     36                   // BM x 36 words per A stage (pad 4)
#define B_LDW     136                  // BK x 136 words per B stage (pad 8)
#define A_STAGE_W (BM * A_LDW)
#define B_STAGE_W (BK * B_LDW)
#define NSTAGE    3
#define SMEM_WORDS (NSTAGE * (A_STAGE_W + B_STAGE_W) + BM)
#define SMEM_BYTES (SMEM_WORDS * 4)

// ---------------------------------------------------------------------------
// Utilities
// ---------------------------------------------------------------------------
__device__ __forceinline__ unsigned f2tf(float f) {
    unsigned u;
    asm("cvt.rna.tf32.f32 %0, %1;" : "=r"(u) : "f"(f));
    return u;
}

__device__ __forceinline__ void mma_tf32(float* d, const unsigned* a, const unsigned* b) {
    asm volatile(
        "mma.sync.aligned.m16n8k8.row.col.f32.tf32.tf32.f32 "
        "{%0,%1,%2,%3}, {%4,%5,%6,%7}, {%8,%9}, {%0,%1,%2,%3};"
        : "+f"(d[0]), "+f"(d[1]), "+f"(d[2]), "+f"(d[3])
        : "r"(a[0]), "r"(a[1]), "r"(a[2]), "r"(a[3]),
          "r"(b[0]), "r"(b[1]));
}

__device__ __forceinline__ void cp16(void* smem_dst, const void* gmem_src) {
    uint32_t sa = (uint32_t)__cvta_generic_to_shared(smem_dst);
    asm volatile("cp.async.cg.shared.global [%0], [%1], 16;\n"
                 :: "r"(sa), "l"(gmem_src));
}
__device__ __forceinline__ void cp_commit() {
    asm volatile("cp.async.commit_group;\n" ::: "memory");
}
__device__ __forceinline__ void cp_wait1() {
    asm volatile("cp.async.wait_group 1;\n" ::: "memory");
}

// ---------------------------------------------------------------------------
// Kernel 0: reset routing state (must happen every replay)
// ---------------------------------------------------------------------------
__global__ __launch_bounds__(32) void reset_kernel() {
    int idx = threadIdx.x;
    if (idx < NE) { g_counts[idx] = 0; g_fill[idx] = 0; }
}

// ---------------------------------------------------------------------------
// Kernel 0b: pre-round W1 and W2 to tf32 bit patterns (one float4 per thread)
// ---------------------------------------------------------------------------
__global__ __launch_bounds__(256) void round_w_kernel(
        const float* __restrict__ W1, const float* __restrict__ W2) {
    int i = blockIdx.x * blockDim.x + threadIdx.x;     // W_ELEMS/4 threads
    float4 v = reinterpret_cast<const float4*>(W1)[i];
    reinterpret_cast<uint4*>(g_w1r)[i] =
        make_uint4(f2tf(v.x), f2tf(v.y), f2tf(v.z), f2tf(v.w));
    float4 u = reinterpret_cast<const float4*>(W2)[i];
    reinterpret_cast<uint4*>(g_w2r)[i] =
        make_uint4(f2tf(u.x), f2tf(u.y), f2tf(u.z), f2tf(u.w));
}

// ---------------------------------------------------------------------------
// Kernel 1: router — one warp per token. Also emits tf32-rounded x.
// ---------------------------------------------------------------------------
__global__ __launch_bounds__(256) void router_kernel(
        const float* __restrict__ x,
        const float* __restrict__ Wr,
        const float* __restrict__ br) {
    int warp = (blockIdx.x * blockDim.x + threadIdx.x) >> 5;
    int lane = threadIdx.x & 31;
    if (warp >= T_TOK) return;

    const float* xr = x + (size_t)warp * D_IN;
    float* xo       = g_xr + (size_t)warp * D_IN;
    float acc[NE];
#pragma unroll
    for (int e = 0; e < NE; e++) acc[e] = 0.0f;

    for (int k = lane; k < D_IN; k += 32) {
        float xv = xr[k];
        xo[k] = __uint_as_float(f2tf(xv));          // rounded copy for GEMM1
        const float* w = Wr + (size_t)k * NE;
#pragma unroll
        for (int e = 0; e < NE; e++) acc[e] = fmaf(xv, w[e], acc[e]);
    }
#pragma unroll
    for (int off = 16; off > 0; off >>= 1) {
#pragma unroll
        for (int e = 0; e < NE; e++)
            acc[e] += __shfl_xor_sync(0xffffffffu, acc[e], off);
    }
    if (lane == 0) {
        float v0 = -3.4e38f, v1 = -3.4e38f;
        int   i0 = 0, i1 = 0;
#pragma unroll
        for (int e = 0; e < NE; e++) {
            float v = acc[e] + br[e];
            if (v > v0)      { v1 = v0; i1 = i0; v0 = v; i0 = e; }
            else if (v > v1) { v1 = v;  i1 = e; }
        }
        float ex  = expf(v1 - v0);
        float inv = 1.0f / (1.0f + ex);
        g_tok_e[2 * warp]     = i0;  g_tok_w[2 * warp]     = inv;
        g_tok_e[2 * warp + 1] = i1;  g_tok_w[2 * warp + 1] = ex * inv;
        atomicAdd(&g_counts[i0], 1);
        atomicAdd(&g_counts[i1], 1);
    }
}

// ---------------------------------------------------------------------------
// Kernel 2: exclusive scan over 8 counts
// ---------------------------------------------------------------------------
__global__ __launch_bounds__(32) void scan_kernel() {
    if (threadIdx.x == 0) {
        int s = 0;
        for (int e = 0; e < NE; e++) { g_base[e] = s; s += g_counts[e]; }
    }
}

// ---------------------------------------------------------------------------
// Kernel 3: scatter tokens into per-expert contiguous slot lists.
// Records both directions: slot -> token/weight, token -> slot.
// ---------------------------------------------------------------------------
__global__ __launch_bounds__(256) void scatter_kernel() {
    int t = blockIdx.x * blockDim.x + threadIdx.x;
    if (t >= T_TOK) return;
#pragma unroll
    for (int k = 0; k < 2; k++) {
        int   e = g_tok_e[2 * t + k];
        float w = g_tok_w[2 * t + k];
        int pos = atomicAdd(&g_fill[e], 1);
        int s   = g_base[e] + pos;
        g_slot_token[s]     = t;
        g_slot_w[s]         = w;
        g_tok_slot[2 * t + k] = s;
    }
}

// ---------------------------------------------------------------------------
// GEMM fragment compute on one resident stage. All operands pre-rounded:
// raw 32-bit loads feed mma directly (no cvt).
// Warp (wm, wn) computes a 64x32 patch: 4 x (m16) by 4 x (n8).
// ---------------------------------------------------------------------------
__device__ __forceinline__ void compute_stage(
        const unsigned* __restrict__ sA, const unsigned* __restrict__ sB,
        int wm, int wn, int gq, int tq, float cfr[4][4][4]) {
#pragma unroll
    for (int ks = 0; ks < 4; ks++) {
        const int kk = ks * 8;
        unsigned a[4][4], b[4][2];
#pragma unroll
        for (int im = 0; im < 4; im++) {
            int r = wm * 64 + im * 16 + gq;
            a[im][0] = sA[(size_t)r * A_LDW + kk + tq];
            a[im][1] = sA[(size_t)(r + 8) * A_LDW + kk + tq];
            a[im][2] = sA[(size_t)r * A_LDW + kk + tq + 4];
            a[im][3] = sA[(size_t)(r + 8) * A_LDW + kk + tq + 4];
        }
#pragma unroll
        for (int jn = 0; jn < 4; jn++) {
            int col = wn * 32 + jn * 8 + gq;
            b[jn][0] = sB[(size_t)(kk + tq) * B_LDW + col];
            b[jn][1] = sB[(size_t)(kk + tq + 4) * B_LDW + col];
        }
#pragma unroll
        for (int im = 0; im < 4; im++)
#pragma unroll
            for (int jn = 0; jn < 4; jn++)
                mma_tf32(cfr[im][jn], a[im], b[jn]);
    }
}

// ---------------------------------------------------------------------------
// Kernel 4: GEMM1  g_h[slot, :] = tf32_round(relu(g_xr[token] @ g_w1r[e] + b1[e]))
// ---------------------------------------------------------------------------
__global__ __launch_bounds__(NTHREADS, 1) void gemm1_kernel(
        const float* __restrict__ b1) {
    const int e     = blockIdx.z;
    const int count = g_counts[e];
    const int row0  = blockIdx.y * BM;
    if (row0 >= count) return;
    const int n0   = blockIdx.x * BN;
    const int base = g_base[e];

    extern __shared__ float smem[];
    float* sA   = smem;
    float* sB   = smem + NSTAGE * A_STAGE_W;
    int*   toks = (int*)(sB + NSTAGE * B_STAGE_W);   // BM entries

    const int tid = threadIdx.x;
    if (tid < BM) {
        int r = row0 + tid;
        toks[tid] = (r < count) ? g_slot_token[base + r] : g_slot_token[base];
    }
    __syncthreads();

    const int NK = D_IN / BK;   // 32
    const float* Wb = g_w1r + (size_t)e * D_IN * D_FF;

    const int ar = tid >> 3, ac = (tid & 7) << 2;     // A: BM rows x 8 float4
    const int bkr = tid >> 5, bc = (tid & 31) << 2;   // B: 32 rows x 32 float4

#define G1_LOAD(KIDX)                                                          \
    do {                                                                       \
        int _k = (KIDX);                                                       \
        if (_k < NK) {                                                         \
            int _s = _k % NSTAGE;                                              \
            float* _dA = sA + (size_t)_s * A_STAGE_W;                          \
            float* _dB = sB + (size_t)_s * B_STAGE_W;                          \
            int _k0 = _k * BK;                                                 \
            _Pragma("unroll")                                                  \
            for (int _i = 0; _i < 4; _i++) {                                   \
                int _r = ar + _i * 64;                                         \
                cp16(&_dA[(size_t)_r * A_LDW + ac],                            \
                     g_xr + (size_t)toks[_r] * D_IN + _k0 + ac);               \
            }                                                                  \
            _Pragma("unroll")                                                  \
            for (int _i = 0; _i < 2; _i++) {                                   \
                int _kr = bkr + _i * 16;                                       \
                cp16(&_dB[(size_t)_kr * B_LDW + bc],                           \
                     Wb + (size_t)(_k0 + _kr) * D_FF + n0 + bc);               \
            }                                                                  \
        }                                                                      \
        cp_commit();                                                           \
    } while (0)

    const int wid = tid >> 5, lane = tid & 31;
    const int wm = wid & 3, wn = wid >> 2;          // 4 x 4 warps
    const int gq = lane >> 2, tq = lane & 3;

    float cfr[4][4][4];
#pragma unroll
    for (int im = 0; im < 4; im++)
#pragma unroll
        for (int jn = 0; jn < 4; jn++)
#pragma unroll
            for (int q = 0; q < 4; q++) cfr[im][jn][q] = 0.0f;

    G1_LOAD(0);
    G1_LOAD(1);
#pragma unroll 1
    for (int k = 0; k < NK; k++) {
        cp_wait1();
        __syncthreads();
        G1_LOAD(k + 2);
        int s = k % NSTAGE;
        compute_stage((const unsigned*)(sA + (size_t)s * A_STAGE_W),
                      (const unsigned*)(sB + (size_t)s * B_STAGE_W),
                      wm, wn, gq, tq, cfr);
    }
#undef G1_LOAD

    // Epilogue: bias + relu + tf32 rounding, float2 stores to g_h
#pragma unroll
    for (int im = 0; im < 4; im++) {
        int rA = row0 + wm * 64 + im * 16 + gq;
        int rB = rA + 8;
#pragma unroll
        for (int jn = 0; jn < 4; jn++) {
            int cc  = n0 + wn * 32 + jn * 8 + 2 * tq;
            float b0v = __ldg(&b1[e * D_FF + cc]);
            float b1v = __ldg(&b1[e * D_FF + cc + 1]);
            if (rA < count) {
                float2 v = make_float2(
                    __uint_as_float(f2tf(fmaxf(cfr[im][jn][0] + b0v, 0.0f))),
                    __uint_as_float(f2tf(fmaxf(cfr[im][jn][1] + b1v, 0.0f))));
                *reinterpret_cast<float2*>(&g_h[(size_t)(base + rA) * D_FF + cc]) = v;
            }
            if (rB < count) {
                float2 v = make_float2(
                    __uint_as_float(f2tf(fmaxf(cfr[im][jn][2] + b0v, 0.0f))),
                    __uint_as_float(f2tf(fmaxf(cfr[im][jn][3] + b1v, 0.0f))));
                *reinterpret_cast<float2*>(&g_h[(size_t)(base + rB) * D_FF + cc]) = v;
            }
        }
    }
}

// ---------------------------------------------------------------------------
// Kernel 5: GEMM2  g_part[slot, :] = w_slot * (g_h[slot] @ g_w2r[e] + b2[e])
// No atomics: plain float2 stores to per-slot scratch.
// ---------------------------------------------------------------------------
__global__ __launch_bounds__(NTHREADS, 1) void gemm2_kernel(
        const float* __restrict__ b2) {
    const int e     = blockIdx.z;
    const int count = g_counts[e];
    const int row0  = blockIdx.y * BM;
    if (row0 >= count) return;
    const int n0   = blockIdx.x * BN;
    const int base = g_base[e];

    extern __shared__ float smem[];
    float* sA    = smem;
    float* sB    = smem + NSTAGE * A_STAGE_W;
    int*   slots = (int*)(sB + NSTAGE * B_STAGE_W);

    const int tid = threadIdx.x;
    if (tid < BM) {
        int r = row0 + tid;
        slots[tid] = base + ((r < count) ? r : (count - 1));
    }
    __syncthreads();

    const int NK = D_FF / BK;   // 128
    const float* Wb = g_w2r + (size_t)e * D_FF * D_IN;

    const int ar = tid >> 3, ac = (tid & 7) << 2;
    const int bkr = tid >> 5, bc = (tid & 31) << 2;

#define G2_LOAD(KIDX)                                                          \
    do {                                                                       \
        int _k = (KIDX);                                                       \
        if (_k < NK) {                                                         \
            int _s = _k % NSTAGE;                                              \
            float* _dA = sA + (size_t)_s * A_STAGE_W;                          \
            float* _dB = sB + (size_t)_s * B_STAGE_W;                          \
            int _k0 = _k * BK;                                                 \
            _Pragma("unroll")                                                  \
            for (int _i = 0; _i < 4; _i++) {                                   \
                int _r = ar + _i * 64;                                         \
                cp16(&_dA[(size_t)_r * A_LDW + ac],                            \
                     g_h + (size_t)slots[_r] * D_FF + _k0 + ac);               \
            }                                                                  \
            _Pragma("unroll")                                                  \
            for (int _i = 0; _i < 2; _i++) {                                   \
                int _kr = bkr + _i * 16;                                       \
                cp16(&_dB[(size_t)_kr * B_LDW + bc],                           \
                     Wb + (size_t)(_k0 + _kr) * D_IN + n0 + bc);               \
            }                                                                  \
        }                                                                      \
        cp_commit();                                                           \
    } while (0)

    const int wid = tid >> 5, lane = tid & 31;
    const int wm = wid & 3, wn = wid >> 2;
    const int gq = lane >> 2, tq = lane & 3;

    float cfr[4][4][4];
#pragma unroll
    for (int im = 0; im < 4; im++)
#pragma unroll
        for (int jn = 0; jn < 4; jn++)
#pragma unroll
            for (int q = 0; q < 4; q++) cfr[im][jn][q] = 0.0f;

    G2_LOAD(0);
    G2_LOAD(1);
#pragma unroll 1
    for (int k = 0; k < NK; k++) {
        cp_wait1();
        __syncthreads();
        G2_LOAD(k + 2);
        int s = k % NSTAGE;
        compute_stage((const unsigned*)(sA + (size_t)s * A_STAGE_W),
                      (const unsigned*)(sB + (size_t)s * B_STAGE_W),
                      wm, wn, gq, tq, cfr);
    }
#undef G2_LOAD

    // Epilogue: bias + router-weight scale, float2 stores to g_part
#pragma unroll
    for (int im = 0; im < 4; im++) {
        int rA = row0 + wm * 64 + im * 16 + gq;
        int rB = rA + 8;
        float wA = (rA < count) ? g_slot_w[base + rA] : 0.0f;
        float wB = (rB < count) ? g_slot_w[base + rB] : 0.0f;
#pragma unroll
        for (int jn = 0; jn < 4; jn++) {
            int cc  = n0 + wn * 32 + jn * 8 + 2 * tq;
            float bb0 = __ldg(&b2[e * D_IN + cc]);
            float bb1 = __ldg(&b2[e * D_IN + cc + 1]);
            if (rA < count) {
                float2 v = make_float2((cfr[im][jn][0] + bb0) * wA,
                                       (cfr[im][jn][1] + bb1) * wA);
                *reinterpret_cast<float2*>(&g_part[(size_t)(base + rA) * D_IN + cc]) = v;
            }
            if (rB < count) {
                float2 v = make_float2((cfr[im][jn][2] + bb0) * wB,
                                       (cfr[im][jn][3] + bb1) * wB);
                *reinterpret_cast<float2*>(&g_part[(size_t)(base + rB) * D_IN + cc]) = v;
            }
        }
    }
}

// ---------------------------------------------------------------------------
// Kernel 6: combine — out[t, :] = g_part[slot0(t), :] + g_part[slot1(t), :]
// Pure streaming, float4 vectorized. Fully overwrites d_out (no pre-zero).
// ---------------------------------------------------------------------------
__global__ __launch_bounds__(256) void combine_kernel(float* __restrict__ out) {
    int idx = blockIdx.x * blockDim.x + threadIdx.x;   // T_TOK * 256 threads
    int t   = idx >> 8;                                 // D_IN/4 = 256 per token
    int c4  = (idx & 255) << 2;
    if (t >= T_TOK) return;
    int s0 = g_tok_slot[2 * t];
    int s1 = g_tok_slot[2 * t + 1];
    float4 a = *reinterpret_cast<const float4*>(&g_part[(size_t)s0 * D_IN + c4]);
    float4 b = *reinterpret_cast<const float4*>(&g_part[(size_t)s1 * D_IN + c4]);
    float4 r = make_float4(a.x + b.x, a.y + b.y, a.z + b.z, a.w + b.w);
    *reinterpret_cast<float4*>(&out[(size_t)t * D_IN + c4]) = r;
}

// ---------------------------------------------------------------------------
// Launch
// ---------------------------------------------------------------------------
extern "C" void kernel_launch(void* const* d_in, const int* in_sizes, int n_in,
                              void* d_out, int out_size) {
    const float* x  = (const float*)d_in[0];
    const float* Wr = (const float*)d_in[1];
    const float* br = (const float*)d_in[2];
    const float* W1 = (const float*)d_in[3];
    const float* b1 = (const float*)d_in[4];
    const float* W2 = (const float*)d_in[5];
    const float* b2 = (const float*)d_in[6];
    float* out = (float*)d_out;

    // Attribute sets (not allocations; idempotent, capture-safe)
    cudaFuncSetAttribute(gemm1_kernel,
                         cudaFuncAttributeMaxDynamicSharedMemorySize, SMEM_BYTES);
    cudaFuncSetAttribute(gemm2_kernel,
                         cudaFuncAttributeMaxDynamicSharedMemorySize, SMEM_BYTES);

    reset_kernel<<<1, 32>>>();
    round_w_kernel<<<(W_ELEMS / 4) / 256, 256>>>(W1, W2);
    router_kernel<<<T_TOK / 8, 256>>>(x, Wr, br);
    scan_kernel<<<1, 32>>>();
    scatter_kernel<<<T_TOK / 256, 256>>>();
    gemm1_kernel<<<dim3(D_FF / BN, T_TOK / BM, NE), NTHREADS, SMEM_BYTES>>>(b1);
    gemm2_kernel<<<dim3(D_IN / BN, T_TOK / BM, NE), NTHREADS, SMEM_BYTES>>>(b2);
    combine_kernel<<<T_TOK, 256>>>(out);
}

// round 13
// speedup vs baseline: 1.4761x; 1.4761x over previous
#include <cuda_runtime.h>
#include <cuda_fp16.h>
#include <math.h>
#include <stdint.h>

// ---------------------------------------------------------------------------
// SparseMoE top-2-of-8, T=8192, D=1024, D_FF=4096, fp32 in/out.
// Sparse grouped-GEMM, fp16 mma.sync m16n8k16 (fp32 accumulate).
// All operands pre-converted to fp16 in memory; weights pre-transposed [N][K].
// BM=256 x BN=128 x BK=32, 512 threads, 3-stage cp.async pipeline.
// GEMM2 writes per-slot partials; combine kernel sums each token's 2 slots.
// ---------------------------------------------------------------------------

#define T_TOK 8192
#define D_IN  1024
#define D_FF  4096
#define NE    8
#define NSLOT (T_TOK * 2)
#define W_ELEMS (NE * D_IN * D_FF)

__device__ int    g_counts[NE];
__device__ int    g_base[NE];
__device__ int    g_fill[NE];
__device__ int    g_tok_e[NSLOT];
__device__ float  g_tok_w[NSLOT];
__device__ int    g_tok_slot[NSLOT];
__device__ float  g_slot_w[NSLOT];
__device__ int    g_slot_token[NSLOT];
__device__ __half g_h[(size_t)NSLOT * D_FF];     // fp16 hidden acts
__device__ float  g_part[(size_t)NSLOT * D_IN];  // per-slot weighted outputs
__device__ __half g_xr[(size_t)T_TOK * D_IN];    // fp16 x
__device__ __half g_w1r[(size_t)W_ELEMS];        // W1^T [E][4096][1024] fp16
__device__ __half g_w2r[(size_t)W_ELEMS];        // W2^T [E][1024][4096] fp16

// Tile geometry
#define BM        256
#define BN        128
#define BK        32
#define NTHREADS  512
#define A_PITCH_W 20                    // 80 bytes/row (64 data + 16 pad) in uints
#define B_PITCH_W 20
#define A_STAGE_W (BM * A_PITCH_W)      // 5120 uints
#define B_STAGE_W (BN * B_PITCH_W)      // 2560 uints
#define NSTAGE    3
#define SMEM_WORDS (NSTAGE * (A_STAGE_W + B_STAGE_W) + BM)
#define SMEM_BYTES (SMEM_WORDS * 4)

// ---------------------------------------------------------------------------
// Utilities
// ---------------------------------------------------------------------------
__device__ __forceinline__ void mma_f16(float* d, const unsigned* a, const unsigned* b) {
    asm volatile(
        "mma.sync.aligned.m16n8k16.row.col.f32.f16.f16.f32 "
        "{%0,%1,%2,%3}, {%4,%5,%6,%7}, {%8,%9}, {%0,%1,%2,%3};"
        : "+f"(d[0]), "+f"(d[1]), "+f"(d[2]), "+f"(d[3])
        : "r"(a[0]), "r"(a[1]), "r"(a[2]), "r"(a[3]),
          "r"(b[0]), "r"(b[1]));
}

__device__ __forceinline__ void cp16(void* smem_dst, const void* gmem_src) {
    uint32_t sa = (uint32_t)__cvta_generic_to_shared(smem_dst);
    asm volatile("cp.async.cg.shared.global [%0], [%1], 16;\n"
                 :: "r"(sa), "l"(gmem_src));
}
__device__ __forceinline__ void cp_commit() {
    asm volatile("cp.async.commit_group;\n" ::: "memory");
}
__device__ __forceinline__ void cp_wait1() {
    asm volatile("cp.async.wait_group 1;\n" ::: "memory");
}

// ---------------------------------------------------------------------------
// Kernel 0: reset routing state
// ---------------------------------------------------------------------------
__global__ __launch_bounds__(32) void reset_kernel() {
    if (threadIdx.x < NE) { g_counts[threadIdx.x] = 0; g_fill[threadIdx.x] = 0; }
}

// ---------------------------------------------------------------------------
// Kernel 0b: transpose + fp16-convert weights. src [E][K][N] -> dst [E][N][K]
// ---------------------------------------------------------------------------
__global__ __launch_bounds__(256) void transpose_h_kernel(
        const float* __restrict__ src, __half* __restrict__ dst, int K, int N) {
    __shared__ float t[32][33];
    int e = blockIdx.z;
    int n0 = blockIdx.x * 32, k0 = blockIdx.y * 32;
    int tx = threadIdx.x & 31, ty = threadIdx.x >> 5;
    const float* s = src + (size_t)e * K * N;
    __half* d = dst + (size_t)e * K * N;
#pragma unroll
    for (int i = 0; i < 32; i += 8)
        t[ty + i][tx] = s[(size_t)(k0 + ty + i) * N + n0 + tx];
    __syncthreads();
#pragma unroll
    for (int i = 0; i < 32; i += 8)
        d[(size_t)(n0 + ty + i) * K + k0 + tx] = __float2half_rn(t[tx][ty + i]);
}

// ---------------------------------------------------------------------------
// Kernel 1: router — one warp per token. Also emits fp16 x.
// ---------------------------------------------------------------------------
__global__ __launch_bounds__(256) void router_kernel(
        const float* __restrict__ x, const float* __restrict__ Wr,
        const float* __restrict__ br) {
    int warp = (blockIdx.x * blockDim.x + threadIdx.x) >> 5;
    int lane = threadIdx.x & 31;
    if (warp >= T_TOK) return;
    const float* xr = x + (size_t)warp * D_IN;
    __half* xo = g_xr + (size_t)warp * D_IN;
    float acc[NE];
#pragma unroll
    for (int e = 0; e < NE; e++) acc[e] = 0.0f;
    for (int k = lane; k < D_IN; k += 32) {
        float xv = xr[k];
        xo[k] = __float2half_rn(xv);
        const float* w = Wr + (size_t)k * NE;
#pragma unroll
        for (int e = 0; e < NE; e++) acc[e] = fmaf(xv, w[e], acc[e]);
    }
#pragma unroll
    for (int off = 16; off > 0; off >>= 1)
#pragma unroll
        for (int e = 0; e < NE; e++)
            acc[e] += __shfl_xor_sync(0xffffffffu, acc[e], off);
    if (lane == 0) {
        float v0 = -3.4e38f, v1 = -3.4e38f; int i0 = 0, i1 = 0;
#pragma unroll
        for (int e = 0; e < NE; e++) {
            float v = acc[e] + br[e];
            if (v > v0)      { v1 = v0; i1 = i0; v0 = v; i0 = e; }
            else if (v > v1) { v1 = v;  i1 = e; }
        }
        float ex = expf(v1 - v0), inv = 1.0f / (1.0f + ex);
        g_tok_e[2 * warp] = i0;     g_tok_w[2 * warp] = inv;
        g_tok_e[2 * warp + 1] = i1; g_tok_w[2 * warp + 1] = ex * inv;
        atomicAdd(&g_counts[i0], 1);
        atomicAdd(&g_counts[i1], 1);
    }
}

// ---------------------------------------------------------------------------
// Kernel 2/3: scan + scatter
// ---------------------------------------------------------------------------
__global__ __launch_bounds__(32) void scan_kernel() {
    if (threadIdx.x == 0) {
        int s = 0;
        for (int e = 0; e < NE; e++) { g_base[e] = s; s += g_counts[e]; }
    }
}

__global__ __launch_bounds__(256) void scatter_kernel() {
    int t = blockIdx.x * blockDim.x + threadIdx.x;
    if (t >= T_TOK) return;
#pragma unroll
    for (int k = 0; k < 2; k++) {
        int e = g_tok_e[2 * t + k];
        float w = g_tok_w[2 * t + k];
        int pos = atomicAdd(&g_fill[e], 1);
        int s = g_base[e] + pos;
        g_slot_token[s] = t;
        g_slot_w[s] = w;
        g_tok_slot[2 * t + k] = s;
    }
}

// ---------------------------------------------------------------------------
// Fragment compute on one resident stage (fp16 m16n8k16).
// Warp (wm, wn): 64x32 patch = 4 m16 x 4 n8; two k16 steps per BK=32.
// smem viewed as uint32: As[row*20 + k2], Bs[n*20 + k2]  (k2 = k/2)
// ---------------------------------------------------------------------------
__device__ __forceinline__ void compute_stage(
        const unsigned* __restrict__ sA, const unsigned* __restrict__ sB,
        int wm, int wn, int gq, int tq, float cfr[4][4][4]) {
#pragma unroll
    for (int ks = 0; ks < 2; ks++) {
        const int kk = ks * 8;               // uint offset of this k16 step
        unsigned a[4][4], b[4][2];
#pragma unroll
        for (int im = 0; im < 4; im++) {
            int r = wm * 64 + im * 16 + gq;
            a[im][0] = sA[r * A_PITCH_W + kk + tq];
            a[im][1] = sA[(r + 8) * A_PITCH_W + kk + tq];
            a[im][2] = sA[r * A_PITCH_W + kk + tq + 4];
            a[im][3] = sA[(r + 8) * A_PITCH_W + kk + tq + 4];
        }
#pragma unroll
        for (int jn = 0; jn < 4; jn++) {
            int n = wn * 32 + jn * 8 + gq;
            b[jn][0] = sB[n * B_PITCH_W + kk + tq];
            b[jn][1] = sB[n * B_PITCH_W + kk + tq + 4];
        }
#pragma unroll
        for (int im = 0; im < 4; im++)
#pragma unroll
            for (int jn = 0; jn < 4; jn++)
                mma_f16(cfr[im][jn], a[im], b[jn]);
    }
}

// ---------------------------------------------------------------------------
// Grouped GEMM (fp16 operands).
// IS_G1: A = gathered g_xr rows -> out relu+fp16 to g_h
// else : A = contiguous g_h rows -> out (v+b)*w fp32 to g_part
// ---------------------------------------------------------------------------
template <int KDIM, int NCOLS, bool IS_G1>
__global__ __launch_bounds__(NTHREADS, 1) void moe_gemm_h(
        const float* __restrict__ bias) {
    const int e     = blockIdx.z;
    const int count = g_counts[e];
    const int row0  = blockIdx.y * BM;
    if (row0 >= count) return;
    const int n0   = blockIdx.x * BN;
    const int base = g_base[e];

    extern __shared__ unsigned smem[];
    unsigned* sA   = smem;
    unsigned* sB   = smem + NSTAGE * A_STAGE_W;
    int*      toks = (int*)(sB + NSTAGE * B_STAGE_W);   // BM entries

    const int tid = threadIdx.x;
    if (tid < BM) {
        int r = row0 + tid;
        if (IS_G1) toks[tid] = (r < count) ? g_slot_token[base + r] : g_slot_token[base];
        else       toks[tid] = base + ((r < count) ? r : (count - 1));
    }
    __syncthreads();

    const __half* Asrc = IS_G1 ? g_xr : g_h;
    const __half* Bsrc = (IS_G1 ? g_w1r : g_w2r) + (size_t)e * (size_t)KDIM * NCOLS;
    const int NK = KDIM / BK;

    // copy coords: A 256 rows x 4 cp16 (2/thread); B 128 rows x 4 cp16 (1/thread)
    const int ar = tid >> 2, au = tid & 3;

#define G_LOAD(KIDX)                                                           \
    do {                                                                       \
        int _k = (KIDX);                                                       \
        if (_k < NK) {                                                         \
            int _s = _k % NSTAGE;                                              \
            unsigned* _dA = sA + _s * A_STAGE_W;                               \
            unsigned* _dB = sB + _s * B_STAGE_W;                               \
            int _k0 = _k * BK;                                                 \
            _Pragma("unroll")                                                  \
            for (int _i = 0; _i < 2; _i++) {                                   \
                int _r = ar + _i * 128;                                        \
                cp16(&_dA[_r * A_PITCH_W + au * 4],                            \
                     Asrc + (size_t)toks[_r] * KDIM + _k0 + au * 8);           \
            }                                                                  \
            cp16(&_dB[ar * B_PITCH_W + au * 4],                                \
                 Bsrc + (size_t)(n0 + ar) * KDIM + _k0 + au * 8);              \
        }                                                                      \
        cp_commit();                                                           \
    } while (0)

    const int wid = tid >> 5, lane = tid & 31;
    const int wm = wid & 3, wn = wid >> 2;
    const int gq = lane >> 2, tq = lane & 3;

    float cfr[4][4][4];
#pragma unroll
    for (int im = 0; im < 4; im++)
#pragma unroll
        for (int jn = 0; jn < 4; jn++)
#pragma unroll
            for (int q = 0; q < 4; q++) cfr[im][jn][q] = 0.0f;

    G_LOAD(0);
    G_LOAD(1);
#pragma unroll 1
    for (int k = 0; k < NK; k++) {
        cp_wait1();
        __syncthreads();
        G_LOAD(k + 2);
        int s = k % NSTAGE;
        compute_stage(sA + s * A_STAGE_W, sB + s * B_STAGE_W, wm, wn, gq, tq, cfr);
    }
#undef G_LOAD

    // Epilogue
#pragma unroll
    for (int im = 0; im < 4; im++) {
        int rA = row0 + wm * 64 + im * 16 + gq;
        int rB = rA + 8;
        float wA = 0.0f, wB = 0.0f;
        if (!IS_G1) {
            if (rA < count) wA = g_slot_w[base + rA];
            if (rB < count) wB = g_slot_w[base + rB];
        }
#pragma unroll
        for (int jn = 0; jn < 4; jn++) {
            int cc  = n0 + wn * 32 + jn * 8 + 2 * tq;
            float b0v = __ldg(&bias[e * NCOLS + cc]);
            float b1v = __ldg(&bias[e * NCOLS + cc + 1]);
            if (IS_G1) {
                if (rA < count) {
                    __half2 v = __floats2half2_rn(fmaxf(cfr[im][jn][0] + b0v, 0.0f),
                                                  fmaxf(cfr[im][jn][1] + b1v, 0.0f));
                    *reinterpret_cast<__half2*>(&g_h[(size_t)(base + rA) * D_FF + cc]) = v;
                }
                if (rB < count) {
                    __half2 v = __floats2half2_rn(fmaxf(cfr[im][jn][2] + b0v, 0.0f),
                                                  fmaxf(cfr[im][jn][3] + b1v, 0.0f));
                    *reinterpret_cast<__half2*>(&g_h[(size_t)(base + rB) * D_FF + cc]) = v;
                }
            } else {
                if (rA < count) {
                    float2 v = make_float2((cfr[im][jn][0] + b0v) * wA,
                                           (cfr[im][jn][1] + b1v) * wA);
                    *reinterpret_cast<float2*>(&g_part[(size_t)(base + rA) * D_IN + cc]) = v;
                }
                if (rB < count) {
                    float2 v = make_float2((cfr[im][jn][2] + b0v) * wB,
                                           (cfr[im][jn][3] + b1v) * wB);
                    *reinterpret_cast<float2*>(&g_part[(size_t)(base + rB) * D_IN + cc]) = v;
                }
            }
        }
    }
}

// ---------------------------------------------------------------------------
// Kernel: combine — out[t] = g_part[slot0] + g_part[slot1]
// ---------------------------------------------------------------------------
__global__ __launch_bounds__(256) void combine_kernel(float* __restrict__ out) {
    int idx = blockIdx.x * blockDim.x + threadIdx.x;
    int t = idx >> 8;
    int c4 = (idx & 255) << 2;
    if (t >= T_TOK) return;
    int s0 = g_tok_slot[2 * t];
    int s1 = g_tok_slot[2 * t + 1];
    float4 a = *reinterpret_cast<const float4*>(&g_part[(size_t)s0 * D_IN + c4]);
    float4 b = *reinterpret_cast<const float4*>(&g_part[(size_t)s1 * D_IN + c4]);
    *reinterpret_cast<float4*>(&out[(size_t)t * D_IN + c4]) =
        make_float4(a.x + b.x, a.y + b.y, a.z + b.z, a.w + b.w);
}

// ---------------------------------------------------------------------------
// Launch
// ---------------------------------------------------------------------------
extern "C" void kernel_launch(void* const* d_in, const int* in_sizes, int n_in,
                              void* d_out, int out_size) {
    const float* x  = (const float*)d_in[0];
    const float* Wr = (const float*)d_in[1];
    const float* br = (const float*)d_in[2];
    const float* W1 = (const float*)d_in[3];
    const float* b1 = (const float*)d_in[4];
    const float* W2 = (const float*)d_in[5];
    const float* b2 = (const float*)d_in[6];
    float* out = (float*)d_out;

    __half* w1r; cudaGetSymbolAddress((void**)&w1r, g_w1r);
    __half* w2r; cudaGetSymbolAddress((void**)&w2r, g_w2r);

    cudaFuncSetAttribute(moe_gemm_h<1024, 4096, true>,
                         cudaFuncAttributeMaxDynamicSharedMemorySize, SMEM_BYTES);
    cudaFuncSetAttribute(moe_gemm_h<4096, 1024, false>,
                         cudaFuncAttributeMaxDynamicSharedMemorySize, SMEM_BYTES);

    reset_kernel<<<1, 32>>>();
    // W1 [E][1024][4096] -> [E][4096][1024] fp16
    transpose_h_kernel<<<dim3(D_FF / 32, D_IN / 32, NE), 256>>>(W1, w1r, D_IN, D_FF);
    // W2 [E][4096][1024] -> [E][1024][4096] fp16
    transpose_h_kernel<<<dim3(D_IN / 32, D_FF / 32, NE), 256>>>(W2, w2r, D_FF, D_IN);
    router_kernel<<<T_TOK / 8, 256>>>(x, Wr, br);
    scan_kernel<<<1, 32>>>();
    scatter_kernel<<<T_TOK / 256, 256>>>();
    moe_gemm_h<1024, 4096, true><<<dim3(D_FF / BN, T_TOK / BM, NE), NTHREADS, SMEM_BYTES>>>(b1);
    moe_gemm_h<4096, 1024, false><<<dim3(D_IN / BN, T_TOK / BM, NE), NTHREADS, SMEM_BYTES>>>(b2);
    combine_kernel<<<T_TOK, 256>>>(out);
}

// round 14
// speedup vs baseline: 1.7803x; 1.2061x over previous
#include <cuda_runtime.h>
#include <cuda_fp16.h>
#include <math.h>
#include <stdint.h>

// ---------------------------------------------------------------------------
// SparseMoE top-2-of-8, T=8192, D=1024, D_FF=4096, fp32 in/out.
// Sparse grouped-GEMM, fp16 mma.sync m16n8k16 (fp32 accumulate).
// All operands pre-converted to fp16 in memory; weights pre-transposed [N][K].
// BM=256 x BN=128 x BK=64, 512 threads, 3-stage cp.async pipeline.
// GEMM2 writes per-slot partials; combine kernel sums each token's 2 slots.
// ---------------------------------------------------------------------------

#define T_TOK 8192
#define D_IN  1024
#define D_FF  4096
#define NE    8
#define NSLOT (T_TOK * 2)
#define W_ELEMS (NE * D_IN * D_FF)

__device__ int    g_counts[NE];
__device__ int    g_base[NE];
__device__ int    g_fill[NE];
__device__ int    g_tok_e[NSLOT];
__device__ float  g_tok_w[NSLOT];
__device__ int    g_tok_slot[NSLOT];
__device__ float  g_slot_w[NSLOT];
__device__ int    g_slot_token[NSLOT];
__device__ __half g_h[(size_t)NSLOT * D_FF];     // fp16 hidden acts
__device__ float  g_part[(size_t)NSLOT * D_IN];  // per-slot weighted outputs
__device__ __half g_xr[(size_t)T_TOK * D_IN];    // fp16 x
__device__ __half g_w1r[(size_t)W_ELEMS];        // W1^T [E][4096][1024] fp16
__device__ __half g_w2r[(size_t)W_ELEMS];        // W2^T [E][1024][4096] fp16

// Tile geometry
#define BM        256
#define BN        128
#define BK        64
#define NTHREADS  512
#define A_PITCH_W 36                    // 144 B/row (128 data + 16 pad) in uints
#define B_PITCH_W 36
#define A_STAGE_W (BM * A_PITCH_W)      // 9216 uints = 36 KB
#define B_STAGE_W (BN * B_PITCH_W)      // 4608 uints = 18 KB
#define NSTAGE    3
#define SMEM_WORDS (NSTAGE * (A_STAGE_W + B_STAGE_W) + BM)
#define SMEM_BYTES (SMEM_WORDS * 4)     // ~166 KB

// ---------------------------------------------------------------------------
// Utilities
// ---------------------------------------------------------------------------
__device__ __forceinline__ void mma_f16(float* d, const unsigned* a, const unsigned* b) {
    asm volatile(
        "mma.sync.aligned.m16n8k16.row.col.f32.f16.f16.f32 "
        "{%0,%1,%2,%3}, {%4,%5,%6,%7}, {%8,%9}, {%0,%1,%2,%3};"
        : "+f"(d[0]), "+f"(d[1]), "+f"(d[2]), "+f"(d[3])
        : "r"(a[0]), "r"(a[1]), "r"(a[2]), "r"(a[3]),
          "r"(b[0]), "r"(b[1]));
}

__device__ __forceinline__ void cp16(void* smem_dst, const void* gmem_src) {
    uint32_t sa = (uint32_t)__cvta_generic_to_shared(smem_dst);
    asm volatile("cp.async.cg.shared.global [%0], [%1], 16;\n"
                 :: "r"(sa), "l"(gmem_src));
}
__device__ __forceinline__ void cp_commit() {
    asm volatile("cp.async.commit_group;\n" ::: "memory");
}
__device__ __forceinline__ void cp_wait1() {
    asm volatile("cp.async.wait_group 1;\n" ::: "memory");
}

// ---------------------------------------------------------------------------
// Kernel 0: reset routing state
// ---------------------------------------------------------------------------
__global__ __launch_bounds__(32) void reset_kernel() {
    if (threadIdx.x < NE) { g_counts[threadIdx.x] = 0; g_fill[threadIdx.x] = 0; }
}

// ---------------------------------------------------------------------------
// Kernel 0b: transpose + fp16-convert weights. src [E][K][N] -> dst [E][N][K]
// ---------------------------------------------------------------------------
__global__ __launch_bounds__(256) void transpose_h_kernel(
        const float* __restrict__ src, __half* __restrict__ dst, int K, int N) {
    __shared__ float t[32][33];
    int e = blockIdx.z;
    int n0 = blockIdx.x * 32, k0 = blockIdx.y * 32;
    int tx = threadIdx.x & 31, ty = threadIdx.x >> 5;
    const float* s = src + (size_t)e * K * N;
    __half* d = dst + (size_t)e * K * N;
#pragma unroll
    for (int i = 0; i < 32; i += 8)
        t[ty + i][tx] = s[(size_t)(k0 + ty + i) * N + n0 + tx];
    __syncthreads();
#pragma unroll
    for (int i = 0; i < 32; i += 8)
        d[(size_t)(n0 + ty + i) * K + k0 + tx] = __float2half_rn(t[tx][ty + i]);
}

// ---------------------------------------------------------------------------
// Kernel 1: router — one warp per token, Wr staged in smem as [e][k].
// Also emits fp16 x.
// ---------------------------------------------------------------------------
__global__ __launch_bounds__(256) void router_kernel(
        const float* __restrict__ x, const float* __restrict__ Wr,
        const float* __restrict__ br) {
    __shared__ float sWr[NE * D_IN];     // 32 KB, [e][k]
    int tid = threadIdx.x;
    for (int i = tid; i < NE * D_IN; i += 256) {
        int k = i >> 3, e = i & 7;       // coalesced read of Wr[k][e]
        sWr[e * D_IN + k] = Wr[i];
    }
    __syncthreads();

    int warp = (blockIdx.x * blockDim.x + tid) >> 5;
    int lane = tid & 31;
    if (warp >= T_TOK) return;
    const float* xr = x + (size_t)warp * D_IN;
    __half* xo = g_xr + (size_t)warp * D_IN;
    float acc[NE];
#pragma unroll
    for (int e = 0; e < NE; e++) acc[e] = 0.0f;
    for (int k = lane; k < D_IN; k += 32) {
        float xv = xr[k];
        xo[k] = __float2half_rn(xv);
#pragma unroll
        for (int e = 0; e < NE; e++)
            acc[e] = fmaf(xv, sWr[e * D_IN + k], acc[e]);
    }
#pragma unroll
    for (int off = 16; off > 0; off >>= 1)
#pragma unroll
        for (int e = 0; e < NE; e++)
            acc[e] += __shfl_xor_sync(0xffffffffu, acc[e], off);
    if (lane == 0) {
        float v0 = -3.4e38f, v1 = -3.4e38f; int i0 = 0, i1 = 0;
#pragma unroll
        for (int e = 0; e < NE; e++) {
            float v = acc[e] + br[e];
            if (v > v0)      { v1 = v0; i1 = i0; v0 = v; i0 = e; }
            else if (v > v1) { v1 = v;  i1 = e; }
        }
        float ex = expf(v1 - v0), inv = 1.0f / (1.0f + ex);
        g_tok_e[2 * warp] = i0;     g_tok_w[2 * warp] = inv;
        g_tok_e[2 * warp + 1] = i1; g_tok_w[2 * warp + 1] = ex * inv;
        atomicAdd(&g_counts[i0], 1);
        atomicAdd(&g_counts[i1], 1);
    }
}

// ---------------------------------------------------------------------------
// Kernel 2/3: scan + scatter
// ---------------------------------------------------------------------------
__global__ __launch_bounds__(32) void scan_kernel() {
    if (threadIdx.x == 0) {
        int s = 0;
        for (int e = 0; e < NE; e++) { g_base[e] = s; s += g_counts[e]; }
    }
}

__global__ __launch_bounds__(256) void scatter_kernel() {
    int t = blockIdx.x * blockDim.x + threadIdx.x;
    if (t >= T_TOK) return;
#pragma unroll
    for (int k = 0; k < 2; k++) {
        int e = g_tok_e[2 * t + k];
        float w = g_tok_w[2 * t + k];
        int pos = atomicAdd(&g_fill[e], 1);
        int s = g_base[e] + pos;
        g_slot_token[s] = t;
        g_slot_w[s] = w;
        g_tok_slot[2 * t + k] = s;
    }
}

// ---------------------------------------------------------------------------
// Fragment compute on one resident stage (fp16 m16n8k16).
// Warp (wm, wn): 64x32 patch = 4 m16 x 4 n8; four k16 steps per BK=64.
// smem as uint32: As[row*36 + k2], Bs[n*36 + k2]  (k2 = k/2)
// ---------------------------------------------------------------------------
__device__ __forceinline__ void compute_stage(
        const unsigned* __restrict__ sA, const unsigned* __restrict__ sB,
        int wm, int wn, int gq, int tq, float cfr[4][4][4]) {
#pragma unroll
    for (int ks = 0; ks < 4; ks++) {
        const int kk = ks * 8;               // uint offset of this k16 step
        unsigned a[4][4], b[4][2];
#pragma unroll
        for (int im = 0; im < 4; im++) {
            int r = wm * 64 + im * 16 + gq;
            a[im][0] = sA[r * A_PITCH_W + kk + tq];
            a[im][1] = sA[(r + 8) * A_PITCH_W + kk + tq];
            a[im][2] = sA[r * A_PITCH_W + kk + tq + 4];
            a[im][3] = sA[(r + 8) * A_PITCH_W + kk + tq + 4];
        }
#pragma unroll
        for (int jn = 0; jn < 4; jn++) {
            int n = wn * 32 + jn * 8 + gq;
            b[jn][0] = sB[n * B_PITCH_W + kk + tq];
            b[jn][1] = sB[n * B_PITCH_W + kk + tq + 4];
        }
#pragma unroll
        for (int im = 0; im < 4; im++)
#pragma unroll
            for (int jn = 0; jn < 4; jn++)
                mma_f16(cfr[im][jn], a[im], b[jn]);
    }
}

// ---------------------------------------------------------------------------
// Grouped GEMM (fp16 operands).
// IS_G1: A = gathered g_xr rows -> out relu+fp16 to g_h
// else : A = contiguous g_h rows -> out (v+b)*w fp32 to g_part
// ---------------------------------------------------------------------------
template <int KDIM, int NCOLS, bool IS_G1>
__global__ __launch_bounds__(NTHREADS, 1) void moe_gemm_h(
        const float* __restrict__ bias) {
    const int e     = blockIdx.z;
    const int count = g_counts[e];
    const int row0  = blockIdx.y * BM;
    if (row0 >= count) return;
    const int n0   = blockIdx.x * BN;
    const int base = g_base[e];

    extern __shared__ unsigned smem[];
    unsigned* sA   = smem;
    unsigned* sB   = smem + NSTAGE * A_STAGE_W;
    int*      toks = (int*)(sB + NSTAGE * B_STAGE_W);   // BM entries

    const int tid = threadIdx.x;
    if (tid < BM) {
        int r = row0 + tid;
        if (IS_G1) toks[tid] = (r < count) ? g_slot_token[base + r] : g_slot_token[base];
        else       toks[tid] = base + ((r < count) ? r : (count - 1));
    }
    __syncthreads();

    const __half* Asrc = IS_G1 ? g_xr : g_h;
    const __half* Bsrc = (IS_G1 ? g_w1r : g_w2r) + (size_t)e * (size_t)KDIM * NCOLS;
    const int NK = KDIM / BK;

    // copy coords: id = tid + i*512; row = id>>3, 16B-unit u = id&7
    // A: 256 rows x 8 units = 2048 cp16 -> 4/thread; B: 128 x 8 = 1024 -> 2/thread
    const int ar = tid >> 3, au = tid & 7;

#define G_LOAD(KIDX)                                                           \
    do {                                                                       \
        int _k = (KIDX);                                                       \
        if (_k < NK) {                                                         \
            int _s = _k % NSTAGE;                                              \
            unsigned* _dA = sA + _s * A_STAGE_W;                               \
            unsigned* _dB = sB + _s * B_STAGE_W;                               \
            int _k0 = _k * BK;                                                 \
            _Pragma("unroll")                                                  \
            for (int _i = 0; _i < 4; _i++) {                                   \
                int _r = ar + _i * 64;                                         \
                cp16(&_dA[_r * A_PITCH_W + au * 4],                            \
                     Asrc + (size_t)toks[_r] * KDIM + _k0 + au * 8);           \
            }                                                                  \
            _Pragma("unroll")                                                  \
            for (int _i = 0; _i < 2; _i++) {                                   \
                int _r = ar + _i * 64;                                         \
                cp16(&_dB[_r * B_PITCH_W + au * 4],                            \
                     Bsrc + (size_t)(n0 + _r) * KDIM + _k0 + au * 8);          \
            }                                                                  \
        }                                                                      \
        cp_commit();                                                           \
    } while (0)

    const int wid = tid >> 5, lane = tid & 31;
    const int wm = wid & 3, wn = wid >> 2;
    const int gq = lane >> 2, tq = lane & 3;

    float cfr[4][4][4];
#pragma unroll
    for (int im = 0; im < 4; im++)
#pragma unroll
        for (int jn = 0; jn < 4; jn++)
#pragma unroll
            for (int q = 0; q < 4; q++) cfr[im][jn][q] = 0.0f;

    G_LOAD(0);
    G_LOAD(1);
#pragma unroll 1
    for (int k = 0; k < NK; k++) {
        cp_wait1();
        __syncthreads();
        G_LOAD(k + 2);
        int s = k % NSTAGE;
        compute_stage(sA + s * A_STAGE_W, sB + s * B_STAGE_W, wm, wn, gq, tq, cfr);
    }
#undef G_LOAD

    // Epilogue
#pragma unroll
    for (int im = 0; im < 4; im++) {
        int rA = row0 + wm * 64 + im * 16 + gq;
        int rB = rA + 8;
        float wA = 0.0f, wB = 0.0f;
        if (!IS_G1) {
            if (rA < count) wA = g_slot_w[base + rA];
            if (rB < count) wB = g_slot_w[base + rB];
        }
#pragma unroll
        for (int jn = 0; jn < 4; jn++) {
            int cc  = n0 + wn * 32 + jn * 8 + 2 * tq;
            float b0v = __ldg(&bias[e * NCOLS + cc]);
            float b1v = __ldg(&bias[e * NCOLS + cc + 1]);
            if (IS_G1) {
                if (rA < count) {
                    __half2 v = __floats2half2_rn(fmaxf(cfr[im][jn][0] + b0v, 0.0f),
                                                  fmaxf(cfr[im][jn][1] + b1v, 0.0f));
                    *reinterpret_cast<__half2*>(&g_h[(size_t)(base + rA) * D_FF + cc]) = v;
                }
                if (rB < count) {
                    __half2 v = __floats2half2_rn(fmaxf(cfr[im][jn][2] + b0v, 0.0f),
                                                  fmaxf(cfr[im][jn][3] + b1v, 0.0f));
                    *reinterpret_cast<__half2*>(&g_h[(size_t)(base + rB) * D_FF + cc]) = v;
                }
            } else {
                if (rA < count) {
                    float2 v = make_float2((cfr[im][jn][0] + b0v) * wA,
                                           (cfr[im][jn][1] + b1v) * wA);
                    *reinterpret_cast<float2*>(&g_part[(size_t)(base + rA) * D_IN + cc]) = v;
                }
                if (rB < count) {
                    float2 v = make_float2((cfr[im][jn][2] + b0v) * wB,
                                           (cfr[im][jn][3] + b1v) * wB);
                    *reinterpret_cast<float2*>(&g_part[(size_t)(base + rB) * D_IN + cc]) = v;
                }
            }
        }
    }
}

// ---------------------------------------------------------------------------
// Kernel: combine — out[t] = g_part[slot0] + g_part[slot1]
// ---------------------------------------------------------------------------
__global__ __launch_bounds__(256) void combine_kernel(float* __restrict__ out) {
    int idx = blockIdx.x * blockDim.x + threadIdx.x;
    int t = idx >> 8;
    int c4 = (idx & 255) << 2;
    if (t >= T_TOK) return;
    int s0 = g_tok_slot[2 * t];
    int s1 = g_tok_slot[2 * t + 1];
    float4 a = *reinterpret_cast<const float4*>(&g_part[(size_t)s0 * D_IN + c4]);
    float4 b = *reinterpret_cast<const float4*>(&g_part[(size_t)s1 * D_IN + c4]);
    *reinterpret_cast<float4*>(&out[(size_t)t * D_IN + c4]) =
        make_float4(a.x + b.x, a.y + b.y, a.z + b.z, a.w + b.w);
}

// ---------------------------------------------------------------------------
// Launch
// ---------------------------------------------------------------------------
extern "C" void kernel_launch(void* const* d_in, const int* in_sizes, int n_in,
                              void* d_out, int out_size) {
    const float* x  = (const float*)d_in[0];
    const float* Wr = (const float*)d_in[1];
    const float* br = (const float*)d_in[2];
    const float* W1 = (const float*)d_in[3];
    const float* b1 = (const float*)d_in[4];
    const float* W2 = (const float*)d_in[5];
    const float* b2 = (const float*)d_in[6];
    float* out = (float*)d_out;

    __half* w1r; cudaGetSymbolAddress((void**)&w1r, g_w1r);
    __half* w2r; cudaGetSymbolAddress((void**)&w2r, g_w2r);

    cudaFuncSetAttribute(moe_gemm_h<1024, 4096, true>,
                         cudaFuncAttributeMaxDynamicSharedMemorySize, SMEM_BYTES);
    cudaFuncSetAttribute(moe_gemm_h<4096, 1024, false>,
                         cudaFuncAttributeMaxDynamicSharedMemorySize, SMEM_BYTES);

    reset_kernel<<<1, 32>>>();
    transpose_h_kernel<<<dim3(D_FF / 32, D_IN / 32, NE), 256>>>(W1, w1r, D_IN, D_FF);
    transpose_h_kernel<<<dim3(D_IN / 32, D_FF / 32, NE), 256>>>(W2, w2r, D_FF, D_IN);
    router_kernel<<<T_TOK / 8, 256>>>(x, Wr, br);
    scan_kernel<<<1, 32>>>();
    scatter_kernel<<<T_TOK / 256, 256>>>();
    moe_gemm_h<1024, 4096, true><<<dim3(D_FF / BN, T_TOK / BM, NE), NTHREADS, SMEM_BYTES>>>(b1);
    moe_gemm_h<4096, 1024, false><<<dim3(D_IN / BN, T_TOK / BM, NE), NTHREADS, SMEM_BYTES>>>(b2);
    combine_kernel<<<T_TOK, 256>>>(out);
}

// round 17
// speedup vs baseline: 1.8427x; 1.0350x over previous
#include <cuda_runtime.h>
#include <cuda_fp16.h>
#include <math.h>
#include <stdint.h>

// ---------------------------------------------------------------------------
// SparseMoE top-2-of-8, T=8192, D=1024, D_FF=4096, fp32 in/out.
// fp16 mma.sync m16n8k16 (fp32 accumulate), operands fp16 in memory.
// BM=256 x BN=128 x BK=64, 256 threads / 8 warps, warp tile 64x64,
// 3-stage cp.async pipeline. GEMM2 -> per-slot partials -> combine.
// ---------------------------------------------------------------------------

#define T_TOK 8192
#define D_IN  1024
#define D_FF  4096
#define NE    8
#define NSLOT (T_TOK * 2)
#define W_ELEMS (NE * D_IN * D_FF)

__device__ int    g_counts[NE];
__device__ int    g_base[NE];
__device__ int    g_fill[NE];
__device__ int    g_tok_e[NSLOT];
__device__ float  g_tok_w[NSLOT];
__device__ int    g_tok_slot[NSLOT];
__device__ float  g_slot_w[NSLOT];
__device__ int    g_slot_token[NSLOT];
__device__ __half g_h[(size_t)NSLOT * D_FF];     // fp16 hidden acts
__device__ float  g_part[(size_t)NSLOT * D_IN];  // per-slot weighted outputs
__device__ __half g_xr[(size_t)T_TOK * D_IN];    // fp16 x
__device__ __half g_w1r[(size_t)W_ELEMS];        // W1^T [E][4096][1024] fp16
__device__ __half g_w2r[(size_t)W_ELEMS];        // W2^T [E][1024][4096] fp16

// Tile geometry
#define BM        256
#define BN        128
#define BK        64
#define NTHREADS  256
#define A_PITCH_W 36                    // 144 B/row (128 data + 16 pad) in uints
#define B_PITCH_W 36
#define A_STAGE_W (BM * A_PITCH_W)      // 9216 uints = 36 KB
#define B_STAGE_W (BN * B_PITCH_W)      // 4608 uints = 18 KB
#define NSTAGE    3
#define SMEM_WORDS (NSTAGE * (A_STAGE_W + B_STAGE_W) + BM)
#define SMEM_BYTES (SMEM_WORDS * 4)     // ~166 KB

// ---------------------------------------------------------------------------
// Utilities
// ---------------------------------------------------------------------------
__device__ __forceinline__ void mma_f16(float* d, const unsigned* a, const unsigned* b) {
    asm volatile(
        "mma.sync.aligned.m16n8k16.row.col.f32.f16.f16.f32 "
        "{%0,%1,%2,%3}, {%4,%5,%6,%7}, {%8,%9}, {%0,%1,%2,%3};"
        : "+f"(d[0]), "+f"(d[1]), "+f"(d[2]), "+f"(d[3])
        : "r"(a[0]), "r"(a[1]), "r"(a[2]), "r"(a[3]),
          "r"(b[0]), "r"(b[1]));
}

__device__ __forceinline__ void cp16(void* smem_dst, const void* gmem_src) {
    uint32_t sa = (uint32_t)__cvta_generic_to_shared(smem_dst);
    asm volatile("cp.async.cg.shared.global [%0], [%1], 16;\n"
                 :: "r"(sa), "l"(gmem_src));
}
__device__ __forceinline__ void cp_commit() {
    asm volatile("cp.async.commit_group;\n" ::: "memory");
}
__device__ __forceinline__ void cp_wait1() {
    asm volatile("cp.async.wait_group 1;\n" ::: "memory");
}

// ---------------------------------------------------------------------------
// Kernel 0: reset routing state
// ---------------------------------------------------------------------------
__global__ __launch_bounds__(32) void reset_kernel() {
    if (threadIdx.x < NE) { g_counts[threadIdx.x] = 0; g_fill[threadIdx.x] = 0; }
}

// ---------------------------------------------------------------------------
// Kernel 0b: transpose + fp16-convert weights. src [E][K][N] -> dst [E][N][K]
// ---------------------------------------------------------------------------
__global__ __launch_bounds__(256) void transpose_h_kernel(
        const float* __restrict__ src, __half* __restrict__ dst, int K, int N) {
    __shared__ float t[32][33];
    int e = blockIdx.z;
    int n0 = blockIdx.x * 32, k0 = blockIdx.y * 32;
    int tx = threadIdx.x & 31, ty = threadIdx.x >> 5;
    const float* s = src + (size_t)e * K * N;
    __half* d = dst + (size_t)e * K * N;
#pragma unroll
    for (int i = 0; i < 32; i += 8)
        t[ty + i][tx] = s[(size_t)(k0 + ty + i) * N + n0 + tx];
    __syncthreads();
#pragma unroll
    for (int i = 0; i < 32; i += 8)
        d[(size_t)(n0 + ty + i) * K + k0 + tx] = __float2half_rn(t[tx][ty + i]);
}

// ---------------------------------------------------------------------------
// Kernel 1: router — one warp per token, Wr staged in smem as [e][k].
// Also emits fp16 x.
// ---------------------------------------------------------------------------
__global__ __launch_bounds__(256) void router_kernel(
        const float* __restrict__ x, const float* __restrict__ Wr,
        const float* __restrict__ br) {
    __shared__ float sWr[NE * D_IN];     // 32 KB, [e][k]
    int tid = threadIdx.x;
    for (int i = tid; i < NE * D_IN; i += 256) {
        int k = i >> 3, e = i & 7;
        sWr[e * D_IN + k] = Wr[i];
    }
    __syncthreads();

    int warp = (blockIdx.x * blockDim.x + tid) >> 5;
    int lane = tid & 31;
    if (warp >= T_TOK) return;
    const float* xr = x + (size_t)warp * D_IN;
    __half* xo = g_xr + (size_t)warp * D_IN;
    float acc[NE];
#pragma unroll
    for (int e = 0; e < NE; e++) acc[e] = 0.0f;
    for (int k = lane; k < D_IN; k += 32) {
        float xv = xr[k];
        xo[k] = __float2half_rn(xv);
#pragma unroll
        for (int e = 0; e < NE; e++)
            acc[e] = fmaf(xv, sWr[e * D_IN + k], acc[e]);
    }
#pragma unroll
    for (int off = 16; off > 0; off >>= 1)
#pragma unroll
        for (int e = 0; e < NE; e++)
            acc[e] += __shfl_xor_sync(0xffffffffu, acc[e], off);
    if (lane == 0) {
        float v0 = -3.4e38f, v1 = -3.4e38f; int i0 = 0, i1 = 0;
#pragma unroll
        for (int e = 0; e < NE; e++) {
            float v = acc[e] + br[e];
            if (v > v0)      { v1 = v0; i1 = i0; v0 = v; i0 = e; }
            else if (v > v1) { v1 = v;  i1 = e; }
        }
        float ex = expf(v1 - v0), inv = 1.0f / (1.0f + ex);
        g_tok_e[2 * warp] = i0;     g_tok_w[2 * warp] = inv;
        g_tok_e[2 * warp + 1] = i1; g_tok_w[2 * warp + 1] = ex * inv;
        atomicAdd(&g_counts[i0], 1);
        atomicAdd(&g_counts[i1], 1);
    }
}

// ---------------------------------------------------------------------------
// Kernel 2/3: scan + scatter
// ---------------------------------------------------------------------------
__global__ __launch_bounds__(32) void scan_kernel() {
    if (threadIdx.x == 0) {
        int s = 0;
        for (int e = 0; e < NE; e++) { g_base[e] = s; s += g_counts[e]; }
    }
}

__global__ __launch_bounds__(256) void scatter_kernel() {
    int t = blockIdx.x * blockDim.x + threadIdx.x;
    if (t >= T_TOK) return;
#pragma unroll
    for (int k = 0; k < 2; k++) {
        int e = g_tok_e[2 * t + k];
        float w = g_tok_w[2 * t + k];
        int pos = atomicAdd(&g_fill[e], 1);
        int s = g_base[e] + pos;
        g_slot_token[s] = t;
        g_slot_w[s] = w;
        g_tok_slot[2 * t + k] = s;
    }
}

// ---------------------------------------------------------------------------
// Fragment compute on one resident stage (fp16 m16n8k16).
// 8 warps in 4(m) x 2(n): warp tile 64x64 = 4 m16 x 8 n8; 4 k16 steps.
// smem as uint32: As[row*36 + k2], Bs[n*36 + k2]  (k2 = k/2)
// ---------------------------------------------------------------------------
__device__ __forceinline__ void compute_stage(
        const unsigned* __restrict__ sA, const unsigned* __restrict__ sB,
        int wm, int wn, int gq, int tq, float cfr[4][8][4]) {
#pragma unroll
    for (int ks = 0; ks < 4; ks++) {
        const int kk = ks * 8;
        unsigned a[4][4], b[8][2];
#pragma unroll
        for (int im = 0; im < 4; im++) {
            int r = wm * 64 + im * 16 + gq;
            a[im][0] = sA[r * A_PITCH_W + kk + tq];
            a[im][1] = sA[(r + 8) * A_PITCH_W + kk + tq];
            a[im][2] = sA[r * A_PITCH_W + kk + tq + 4];
            a[im][3] = sA[(r + 8) * A_PITCH_W + kk + tq + 4];
        }
#pragma unroll
        for (int jn = 0; jn < 8; jn++) {
            int n = wn * 64 + jn * 8 + gq;
            b[jn][0] = sB[n * B_PITCH_W + kk + tq];
            b[jn][1] = sB[n * B_PITCH_W + kk + tq + 4];
        }
#pragma unroll
        for (int im = 0; im < 4; im++)
#pragma unroll
            for (int jn = 0; jn < 8; jn++)
                mma_f16(cfr[im][jn], a[im], b[jn]);
    }
}

// ---------------------------------------------------------------------------
// Grouped GEMM (fp16 operands).
// IS_G1: A = gathered g_xr rows -> out relu+fp16 to g_h
// else : A = contiguous g_h rows -> out (v+b)*w fp32 to g_part
// ---------------------------------------------------------------------------
template <int KDIM, int NCOLS, bool IS_G1>
__global__ __launch_bounds__(NTHREADS, 1) void moe_gemm_h(
        const float* __restrict__ bias) {
    const int e     = blockIdx.z;
    const int count = g_counts[e];
    const int row0  = blockIdx.y * BM;
    if (row0 >= count) return;
    const int n0   = blockIdx.x * BN;
    const int base = g_base[e];

    extern __shared__ unsigned smem[];
    unsigned* sA   = smem;
    unsigned* sB   = smem + NSTAGE * A_STAGE_W;
    int*      toks = (int*)(sB + NSTAGE * B_STAGE_W);   // BM entries

    const int tid = threadIdx.x;
    {
        int r = row0 + tid;
        if (IS_G1) toks[tid] = (r < count) ? g_slot_token[base + r] : g_slot_token[base];
        else       toks[tid] = base + ((r < count) ? r : (count - 1));
    }
    __syncthreads();

    const __half* Asrc = IS_G1 ? g_xr : g_h;
    const __half* Bsrc = (IS_G1 ? g_w1r : g_w2r) + (size_t)e * (size_t)KDIM * NCOLS;
    const int NK = KDIM / BK;

    // copy coords: id = tid + i*256; row = id>>3, 16B-unit u = id&7
    // A: 2048 cp16 -> 8/thread; B: 1024 cp16 -> 4/thread
    const int ar = tid >> 3, au = tid & 7;

#define G_LOAD(KIDX)                                                           \
    do {                                                                       \
        int _k = (KIDX);                                                       \
        if (_k < NK) {                                                         \
            int _s = _k % NSTAGE;                                              \
            unsigned* _dA = sA + _s * A_STAGE_W;                               \
            unsigned* _dB = sB + _s * B_STAGE_W;                               \
            int _k0 = _k * BK;                                                 \
            _Pragma("unroll")                                                  \
            for (int _i = 0; _i < 8; _i++) {                                   \
                int _r = ar + _i * 32;                                         \
                cp16(&_dA[_r * A_PITCH_W + au * 4],                            \
                     Asrc + (size_t)toks[_r] * KDIM + _k0 + au * 8);           \
            }                                                                  \
            _Pragma("unroll")                                                  \
            for (int _i = 0; _i < 4; _i++) {                                   \
                int _r = ar + _i * 32;                                         \
                cp16(&_dB[_r * B_PITCH_W + au * 4],                            \
                     Bsrc + (size_t)(n0 + _r) * KDIM + _k0 + au * 8);          \
            }                                                                  \
        }                                                                      \
        cp_commit();                                                           \
    } while (0)

    const int wid = tid >> 5, lane = tid & 31;
    const int wm = wid & 3, wn = wid >> 2;          // 4 x 2 warps
    const int gq = lane >> 2, tq = lane & 3;

    float cfr[4][8][4];
#pragma unroll
    for (int im = 0; im < 4; im++)
#pragma unroll
        for (int jn = 0; jn < 8; jn++)
#pragma unroll
            for (int q = 0; q < 4; q++) cfr[im][jn][q] = 0.0f;

    G_LOAD(0);
    G_LOAD(1);
#pragma unroll 1
    for (int k = 0; k < NK; k++) {
        cp_wait1();
        __syncthreads();
        G_LOAD(k + 2);
        int s = k % NSTAGE;
        compute_stage(sA + s * A_STAGE_W, sB + s * B_STAGE_W, wm, wn, gq, tq, cfr);
    }
#undef G_LOAD

    // Epilogue
#pragma unroll
    for (int im = 0; im < 4; im++) {
        int rA = row0 + wm * 64 + im * 16 + gq;
        int rB = rA + 8;
        float wA = 0.0f, wB = 0.0f;
        if (!IS_G1) {
            if (rA < count) wA = g_slot_w[base + rA];
            if (rB < count) wB = g_slot_w[base + rB];
        }
#pragma unroll
        for (int jn = 0; jn < 8; jn++) {
            int cc  = n0 + wn * 64 + jn * 8 + 2 * tq;
            float b0v = __ldg(&bias[e * NCOLS + cc]);
            float b1v = __ldg(&bias[e * NCOLS + cc + 1]);
            if (IS_G1) {
                if (rA < count) {
                    __half2 v = __floats2half2_rn(fmaxf(cfr[im][jn][0] + b0v, 0.0f),
                                                  fmaxf(cfr[im][jn][1] + b1v, 0.0f));
                    *reinterpret_cast<__half2*>(&g_h[(size_t)(base + rA) * D_FF + cc]) = v;
                }
                if (rB < count) {
                    __half2 v = __floats2half2_rn(fmaxf(cfr[im][jn][2] + b0v, 0.0f),
                                                  fmaxf(cfr[im][jn][3] + b1v, 0.0f));
                    *reinterpret_cast<__half2*>(&g_h[(size_t)(base + rB) * D_FF + cc]) = v;
                }
            } else {
                if (rA < count) {
                    float2 v = make_float2((cfr[im][jn][0] + b0v) * wA,
                                           (cfr[im][jn][1] + b1v) * wA);
                    *reinterpret_cast<float2*>(&g_part[(size_t)(base + rA) * D_IN + cc]) = v;
                }
                if (rB < count) {
                    float2 v = make_float2((cfr[im][jn][2] + b0v) * wB,
                                           (cfr[im][jn][3] + b1v) * wB);
                    *reinterpret_cast<float2*>(&g_part[(size_t)(base + rB) * D_IN + cc]) = v;
                }
            }
        }
    }
}

// ---------------------------------------------------------------------------
// Kernel: combine — out[t] = g_part[slot0] + g_part[slot1]
// ---------------------------------------------------------------------------
__global__ __launch_bounds__(256) void combine_kernel(float* __restrict__ out) {
    int idx = blockIdx.x * blockDim.x + threadIdx.x;
    int t = idx >> 8;
    int c4 = (idx & 255) << 2;
    if (t >= T_TOK) return;
    int s0 = g_tok_slot[2 * t];
    int s1 = g_tok_slot[2 * t + 1];
    float4 a = *reinterpret_cast<const float4*>(&g_part[(size_t)s0 * D_IN + c4]);
    float4 b = *reinterpret_cast<const float4*>(&g_part[(size_t)s1 * D_IN + c4]);
    *reinterpret_cast<float4*>(&out[(size_t)t * D_IN + c4]) =
        make_float4(a.x + b.x, a.y + b.y, a.z + b.z, a.w + b.w);
}

// ---------------------------------------------------------------------------
// Launch
// ---------------------------------------------------------------------------
extern "C" void kernel_launch(void* const* d_in, const int* in_sizes, int n_in,
                              void* d_out, int out_size) {
    const float* x  = (const float*)d_in[0];
    const float* Wr = (const float*)d_in[1];
    const float* br = (const float*)d_in[2];
    const float* W1 = (const float*)d_in[3];
    const float* b1 = (const float*)d_in[4];
    const float* W2 = (const float*)d_in[5];
    const float* b2 = (const float*)d_in[6];
    float* out = (float*)d_out;

    __half* w1r; cudaGetSymbolAddress((void**)&w1r, g_w1r);
    __half* w2r; cudaGetSymbolAddress((void**)&w2r, g_w2r);

    cudaFuncSetAttribute(moe_gemm_h<1024, 4096, true>,
                         cudaFuncAttributeMaxDynamicSharedMemorySize, SMEM_BYTES);
    cudaFuncSetAttribute(moe_gemm_h<4096, 1024, false>,
                         cudaFuncAttributeMaxDynamicSharedMemorySize, SMEM_BYTES);

    reset_kernel<<<1, 32>>>();
    transpose_h_kernel<<<dim3(D_FF / 32, D_IN / 32, NE), 256>>>(W1, w1r, D_IN, D_FF);
    transpose_h_kernel<<<dim3(D_IN / 32, D_FF / 32, NE), 256>>>(W2, w2r, D_FF, D_IN);
    router_kernel<<<T_TOK / 8, 256>>>(x, Wr, br);
    scan_kernel<<<1, 32>>>();
    scatter_kernel<<<T_TOK / 256, 256>>>();
    moe_gemm_h<1024, 4096, true><<<dim3(D_FF / BN, T_TOK / BM, NE), NTHREADS, SMEM_BYTES>>>(b1);
    moe_gemm_h<4096, 1024, false><<<dim3(D_IN / BN, T_TOK / BM, NE), NTHREADS, SMEM_BYTES>>>(b2);
    combine_kernel<<<T_TOK, 256>>>(out);
}